// round 2
// baseline (speedup 1.0000x reference)
#include <cuda_runtime.h>
#include <math.h>

#define SCALE 0.125f
#define EPSA 1e-8f
#define LN_EPS 1e-5f

// scratch (device globals; no allocation allowed)
__device__ float g_slots[64*7*64];
__device__ float g_ug[64*7*64];
__device__ float g_ub[64*7];
__device__ float g_P[256*7*64];   // per (b,chunk) partial numerators
__device__ float g_D[256*7];      // per (b,chunk) partial denominators

// ---------------------------------------------------------------------------
// Kernel 1: per-batch slot-side prep.
// s = LN(slots; g_sl, be_sl); q = s@Wq^T + bq; u = q@Wk
// g_ug = SCALE * u * g_in ; g_ub = SCALE * (u . be_in + q . bk)
// ---------------------------------------------------------------------------
__global__ void slot_prep(const float* __restrict__ noise, const float* __restrict__ mu,
                          const float* __restrict__ sigma,
                          const float* __restrict__ Wq, const float* __restrict__ bq,
                          const float* __restrict__ Wk, const float* __restrict__ bk,
                          const float* __restrict__ g_sl, const float* __restrict__ be_sl,
                          const float* __restrict__ g_in, const float* __restrict__ be_in,
                          int first)
{
    __shared__ float sh_s[7][64];
    __shared__ float sh_q[7][64];
    int b = blockIdx.x;
    int tid = threadIdx.x, w = tid >> 5, lane = tid & 31;

    if (first) {
        for (int idx = tid; idx < 7*64; idx += blockDim.x) {
            int c = idx & 63;
            g_slots[b*448 + idx] = mu[c] + sigma[c] * noise[b*448 + idx];
        }
    }
    __syncthreads();

    if (w < 7) {
        float v0 = g_slots[b*448 + w*64 + lane];
        float v1 = g_slots[b*448 + w*64 + 32 + lane];
        float s = v0 + v1, ss = v0*v0 + v1*v1;
        #pragma unroll
        for (int o = 16; o; o >>= 1) {
            s  += __shfl_xor_sync(0xffffffffu, s,  o);
            ss += __shfl_xor_sync(0xffffffffu, ss, o);
        }
        float m   = s * (1.0f/64.0f);
        float inv = rsqrtf(ss * (1.0f/64.0f) - m*m + LN_EPS);
        sh_s[w][lane]      = (v0 - m)*inv*g_sl[lane]      + be_sl[lane];
        sh_s[w][lane + 32] = (v1 - m)*inv*g_sl[lane + 32] + be_sl[lane + 32];
    }
    __syncthreads();

    if (w < 7) {
        #pragma unroll
        for (int h = 0; h < 2; h++) {
            int c = lane + 32*h;
            float acc = bq[c];
            for (int d = 0; d < 64; d++) acc += sh_s[w][d] * Wq[c*64 + d];
            sh_q[w][c] = acc;
        }
    }
    __syncthreads();

    if (w < 7) {
        float u0 = 0.f, u1 = 0.f;
        for (int c = 0; c < 64; c++) {
            float qv = sh_q[w][c];
            u0 += qv * Wk[c*64 + lane];
            u1 += qv * Wk[c*64 + lane + 32];
        }
        g_ug[b*448 + w*64 + lane]      = u0 * g_in[lane]      * SCALE;
        g_ug[b*448 + w*64 + lane + 32] = u1 * g_in[lane + 32] * SCALE;
        float part = u0*be_in[lane] + u1*be_in[lane+32]
                   + sh_q[w][lane]*bk[lane] + sh_q[w][lane+32]*bk[lane+32];
        #pragma unroll
        for (int o = 16; o; o >>= 1) part += __shfl_xor_sync(0xffffffffu, part, o);
        if (lane == 0) g_ub[b*7 + w] = part * SCALE;
    }
}

// ---------------------------------------------------------------------------
// Kernel 2: the big pass. For each token: LN on the fly, 7 dots vs ug,
// softmax over 7 (+EPS), accumulate P += a * x_hat and denom += a.
// grid = 64 batches x 4 chunks; each CTA: 4 passes of 256 tokens.
// ---------------------------------------------------------------------------
__global__ void __launch_bounds__(256, 2)
attn_pass(const float* __restrict__ inp)
{
    extern __shared__ float sm[];
    float* Xs = sm;                  // [256][68] tokens (raw then normalized)
    float* Ug = Xs + 256*68;         // [7][64]
    float* Ub = Ug + 448;            // [7] (+1 pad)
    float* As = Ub + 8;              // [7][257] attn weights

    int tid = threadIdx.x;
    int blk = blockIdx.x;
    int b = blk >> 2;
    int chunk = blk & 3;

    for (int idx = tid; idx < 448; idx += 256) Ug[idx] = g_ug[b*448 + idx];
    if (tid < 7) Ub[tid] = g_ub[b*7 + tid];

    // P-phase accumulators (threads 0..223): (half over t, i=0..6, c4=0..15)
    float p0=0.f, p1=0.f, p2=0.f, p3=0.f, dsum=0.f;
    int half = tid / 112;
    int rr   = tid - half*112;
    int pi   = rr >> 4;
    int pc4  = rr & 15;

    const float4* in4 = reinterpret_cast<const float4*>(inp)
                      + (size_t)(b*4096 + chunk*1024) * 16;

    for (int pass = 0; pass < 4; pass++) {
        __syncthreads();                       // protect Xs/As vs previous P-phase
        // ---- load 256 tokens, coalesced ----
        const float4* src = in4 + pass*256*16;
        #pragma unroll
        for (int k = 0; k < 16; k++) {
            int idx = tid + k*256;
            int t = idx >> 4, c4 = idx & 15;
            float4 v = src[idx];
            *reinterpret_cast<float4*>(&Xs[t*68 + c4*4]) = v;
        }
        __syncthreads();
        // ---- per-token: LN + dots + softmax ----
        {
            int t = tid;
            float4 xr[16];
            float s = 0.f, ss = 0.f;
            #pragma unroll
            for (int q = 0; q < 16; q++) {
                xr[q] = *reinterpret_cast<float4*>(&Xs[t*68 + q*4]);
                s  += xr[q].x + xr[q].y + xr[q].z + xr[q].w;
                ss += xr[q].x*xr[q].x + xr[q].y*xr[q].y + xr[q].z*xr[q].z + xr[q].w*xr[q].w;
            }
            float m   = s * (1.0f/64.0f);
            float inv = rsqrtf(ss * (1.0f/64.0f) - m*m + LN_EPS);
            float d[7];
            #pragma unroll
            for (int i = 0; i < 7; i++) d[i] = Ub[i];
            #pragma unroll
            for (int q = 0; q < 16; q++) {
                float4 xh;
                xh.x = (xr[q].x - m)*inv;
                xh.y = (xr[q].y - m)*inv;
                xh.z = (xr[q].z - m)*inv;
                xh.w = (xr[q].w - m)*inv;
                #pragma unroll
                for (int i = 0; i < 7; i++) {
                    float4 u = *reinterpret_cast<const float4*>(&Ug[i*64 + q*4]);
                    d[i] += u.x*xh.x + u.y*xh.y + u.z*xh.z + u.w*xh.w;
                }
                *reinterpret_cast<float4*>(&Xs[t*68 + q*4]) = xh;  // store normalized
            }
            float mx = d[0];
            #pragma unroll
            for (int i = 1; i < 7; i++) mx = fmaxf(mx, d[i]);
            float e[7], se = 0.f;
            #pragma unroll
            for (int i = 0; i < 7; i++) { e[i] = __expf(d[i] - mx); se += e[i]; }
            float rinv = 1.0f / se;
            #pragma unroll
            for (int i = 0; i < 7; i++) As[i*257 + t] = e[i]*rinv + EPSA;
        }
        __syncthreads();
        // ---- P accumulation: P[i][c] += a[i][t] * xhat[t][c] ----
        if (tid < 224) {
            int tb = half * 128;
            #pragma unroll 4
            for (int t = 0; t < 128; t++) {
                float a  = As[pi*257 + tb + t];
                float4 x = *reinterpret_cast<float4*>(&Xs[(tb + t)*68 + pc4*4]);
                p0 += a*x.x; p1 += a*x.y; p2 += a*x.z; p3 += a*x.w;
                dsum += a;
            }
        }
    }
    __syncthreads();
    // merge halves, write partials
    if (tid < 224 && half == 1) {
        float* buf = &Xs[rr*8];
        buf[0]=p0; buf[1]=p1; buf[2]=p2; buf[3]=p3; buf[4]=dsum;
    }
    __syncthreads();
    if (tid < 112) {
        float* buf = &Xs[tid*8];
        p0 += buf[0]; p1 += buf[1]; p2 += buf[2]; p3 += buf[3]; dsum += buf[4];
        int o = blk*448 + pi*64 + pc4*4;
        g_P[o+0]=p0; g_P[o+1]=p1; g_P[o+2]=p2; g_P[o+3]=p3;
        if (pc4 == 0) g_D[blk*7 + pi] = dsum;
    }
}

// ---------------------------------------------------------------------------
// Kernel 3: per-batch reduce + Wv projection + GRU + FFN. Deterministic.
// ---------------------------------------------------------------------------
__global__ void slot_update(const float* __restrict__ Wv, const float* __restrict__ bv,
                            const float* __restrict__ W_ih, const float* __restrict__ W_hh,
                            const float* __restrict__ b_ih, const float* __restrict__ b_hh,
                            const float* __restrict__ W1, const float* __restrict__ b1,
                            const float* __restrict__ W2, const float* __restrict__ b2,
                            const float* __restrict__ g_in, const float* __restrict__ be_in,
                            const float* __restrict__ g_ff, const float* __restrict__ be_ff,
                            float* __restrict__ outp)
{
    __shared__ float sP[448];
    __shared__ float sden[7];
    __shared__ float sxa[448];
    __shared__ float supd[448];
    __shared__ float sh_h[448];
    __shared__ float sgi[1344];
    __shared__ float sgh[1344];
    __shared__ float snew[448];
    __shared__ float sff[448];
    __shared__ float sy1[896];
    int b = blockIdx.x, tid = threadIdx.x;

    for (int idx = tid; idx < 448; idx += 256) {
        float s = 0.f;
        #pragma unroll
        for (int ch = 0; ch < 4; ch++) s += g_P[(b*4 + ch)*448 + idx];
        sP[idx] = s;
        sh_h[idx] = g_slots[b*448 + idx];
    }
    if (tid < 7) {
        float s = 0.f;
        #pragma unroll
        for (int ch = 0; ch < 4; ch++) s += g_D[(b*4 + ch)*7 + tid];
        sden[tid] = s;
    }
    __syncthreads();
    // attention-weighted mean back to x-space (g_in, be_in; sum(attn)=1)
    for (int idx = tid; idx < 448; idx += 256) {
        int e = idx & 63, i = idx >> 6;
        sxa[idx] = sP[idx] / sden[i] * g_in[e] + be_in[e];
    }
    __syncthreads();
    // updates = xa @ Wv^T + bv
    for (int idx = tid; idx < 448; idx += 256) {
        int c = idx & 63, i = idx >> 6;
        float acc = bv[c];
        for (int e = 0; e < 64; e++) acc += sxa[i*64 + e] * Wv[c*64 + e];
        supd[idx] = acc;
    }
    __syncthreads();
    // GRU gate pre-activations
    for (int idx = tid; idx < 1344; idx += 256) {
        int i = idx / 192, r = idx - i*192;
        float ai = b_ih[r], ah = b_hh[r];
        for (int c = 0; c < 64; c++) {
            ai += supd[i*64 + c] * W_ih[r*64 + c];
            ah += sh_h[i*64 + c] * W_hh[r*64 + c];
        }
        sgi[idx] = ai; sgh[idx] = ah;
    }
    __syncthreads();
    for (int idx = tid; idx < 448; idx += 256) {
        int c = idx & 63, i = idx >> 6;
        float rg = 1.0f / (1.0f + __expf(-(sgi[i*192 + c]       + sgh[i*192 + c])));
        float zg = 1.0f / (1.0f + __expf(-(sgi[i*192 + 64 + c]  + sgh[i*192 + 64 + c])));
        float ng = tanhf(sgi[i*192 + 128 + c] + rg * sgh[i*192 + 128 + c]);
        snew[idx] = (1.0f - zg)*ng + zg*sh_h[idx];
    }
    __syncthreads();
    // FFN layernorm
    int w = tid >> 5, lane = tid & 31;
    if (w < 7) {
        float v0 = snew[w*64 + lane], v1 = snew[w*64 + 32 + lane];
        float s = v0 + v1, ss = v0*v0 + v1*v1;
        #pragma unroll
        for (int o = 16; o; o >>= 1) {
            s  += __shfl_xor_sync(0xffffffffu, s,  o);
            ss += __shfl_xor_sync(0xffffffffu, ss, o);
        }
        float m   = s * (1.0f/64.0f);
        float inv = rsqrtf(ss * (1.0f/64.0f) - m*m + LN_EPS);
        sff[w*64 + lane]      = (v0 - m)*inv*g_ff[lane]      + be_ff[lane];
        sff[w*64 + lane + 32] = (v1 - m)*inv*g_ff[lane + 32] + be_ff[lane + 32];
    }
    __syncthreads();
    for (int idx = tid; idx < 896; idx += 256) {
        int i = idx >> 7, r = idx & 127;
        float acc = b1[r];
        for (int c = 0; c < 64; c++) acc += sff[i*64 + c] * W1[r*64 + c];
        sy1[idx] = fmaxf(acc, 0.0f);
    }
    __syncthreads();
    for (int idx = tid; idx < 448; idx += 256) {
        int c = idx & 63, i = idx >> 6;
        float acc = b2[c];
        for (int r = 0; r < 128; r++) acc += sy1[i*128 + r] * W2[c*128 + r];
        float v = snew[idx] + acc;
        g_slots[b*448 + idx] = v;
        if (outp) outp[b*448 + idx] = v;
    }
}

// ---------------------------------------------------------------------------
extern "C" void kernel_launch(void* const* d_in, const int* in_sizes, int n_in,
                              void* d_out, int out_size)
{
    const float* inputs = (const float*)d_in[0];
    // d_in[1] = positional_embeddings (unused by reference)
    const float* noise  = (const float*)d_in[2];
    const float* mu     = (const float*)d_in[3];
    const float* sigma  = (const float*)d_in[4];
    const float* Wq     = (const float*)d_in[5];
    const float* bq     = (const float*)d_in[6];
    const float* Wk     = (const float*)d_in[7];
    const float* bk     = (const float*)d_in[8];
    const float* Wv     = (const float*)d_in[9];
    const float* bv     = (const float*)d_in[10];
    const float* W_ih   = (const float*)d_in[11];
    const float* W_hh   = (const float*)d_in[12];
    const float* b_ih   = (const float*)d_in[13];
    const float* b_hh   = (const float*)d_in[14];
    const float* W1     = (const float*)d_in[15];
    const float* b1     = (const float*)d_in[16];
    const float* W2     = (const float*)d_in[17];
    const float* b2     = (const float*)d_in[18];
    const float* gin    = (const float*)d_in[19];
    const float* bein   = (const float*)d_in[20];
    const float* gsl    = (const float*)d_in[21];
    const float* besl   = (const float*)d_in[22];
    const float* gff    = (const float*)d_in[23];
    const float* beff   = (const float*)d_in[24];

    const int SMEM = (256*68 + 448 + 8 + 7*257) * 4;
    cudaFuncSetAttribute(attn_pass, cudaFuncAttributeMaxDynamicSharedMemorySize, SMEM);

    for (int it = 0; it < 3; it++) {
        slot_prep<<<64, 256>>>(noise, mu, sigma, Wq, bq, Wk, bk,
                               gsl, besl, gin, bein, it == 0 ? 1 : 0);
        attn_pass<<<256, 256, SMEM>>>(inputs);
        slot_update<<<64, 256>>>(Wv, bv, W_ih, W_hh, b_ih, b_hh,
                                 W1, b1, W2, b2, gin, bein, gff, beff,
                                 it == 2 ? (float*)d_out : nullptr);
    }
}

// round 3
// speedup vs baseline: 3.4032x; 3.4032x over previous
#include <cuda_runtime.h>
#include <math.h>
typedef unsigned long long ull;

#define SCALE 0.125f
#define EPSA 1e-8f
#define LN_EPS 1e-5f

__device__ __forceinline__ ull fma2(ull a, ull b, ull c){ull d;asm("fma.rn.f32x2 %0,%1,%2,%3;":"=l"(d):"l"(a),"l"(b),"l"(c));return d;}
__device__ __forceinline__ ull add2(ull a, ull b){ull d;asm("add.rn.f32x2 %0,%1,%2;":"=l"(d):"l"(a),"l"(b));return d;}
__device__ __forceinline__ ull pack2(float lo, float hi){ull d;asm("mov.b64 %0,{%1,%2};":"=l"(d):"f"(lo),"f"(hi));return d;}
__device__ __forceinline__ void unpack2(ull v, float& lo, float& hi){asm("mov.b64 {%0,%1},%2;":"=f"(lo),"=f"(hi):"l"(v));}

// device scratch
__device__ float g_slots[64*448];
__device__ ull   g_ug2[64*224];    // pairs of SCALE*u*g_in
__device__ ull   g_ub2[64*7];      // {ub, Su}
__device__ ull   g_P2[256*224];    // per (b,chunk) raw-x weighted sums
__device__ ull   g_KD2[256*7];     // per (b,chunk) {K, D}

// ---------------------------------------------------------------------------
// attn_pass: grid 256 = 64 batches x 4 chunks of 1024 tokens (4 passes of 256)
// ---------------------------------------------------------------------------
__global__ void __launch_bounds__(256,2) attn_pass(const float* __restrict__ inp)
{
    extern __shared__ ull sm[];
    ull* Xs = sm;            // [256][33]: 32 raw-x pairs + {m,std}
    ull* As = sm + 8448;     // [7][257] packed {w,w}
    ull* Ub = sm + 10247;    // [7] {ub,Su}
    ull* Ug = sm + 10254;    // [7][32]

    int tid = threadIdx.x, blk = blockIdx.x;
    int b = blk >> 2, chunk = blk & 3;

    if (tid < 224) Ug[tid] = g_ug2[b*224 + tid];
    if (tid < 7)   Ub[tid] = g_ub2[b*7 + tid];

    ull p2[7]; ull kd2 = 0ull;
    #pragma unroll
    for (int i = 0; i < 7; i++) p2[i] = 0ull;

    const ulonglong2* in4 = (const ulonglong2*)inp + (size_t)(b*4096 + chunk*1024)*16;
    int w8 = tid >> 5, cp = tid & 31;

    for (int pass = 0; pass < 4; pass++) {
        __syncthreads();
        const ulonglong2* src = in4 + pass*256*16;
        #pragma unroll
        for (int k = 0; k < 16; k++) {
            int idx = tid + k*256;
            int t = idx >> 4, c = idx & 15;
            ulonglong2 v = src[idx];
            Xs[t*33 + c*2]     = v.x;
            Xs[t*33 + c*2 + 1] = v.y;
        }
        __syncthreads();
        // token phase: thread t handles token t
        {
            ull* xrow = Xs + tid*33;
            ull sa = 0ull, qa = 0ull, acc[7];
            #pragma unroll
            for (int i = 0; i < 7; i++) acc[i] = 0ull;
            #pragma unroll
            for (int q = 0; q < 32; q++) {
                ull xv = xrow[q];
                sa = add2(sa, xv);
                qa = fma2(xv, xv, qa);
                #pragma unroll
                for (int i = 0; i < 7; i++) acc[i] = fma2(xv, Ug[i*32 + q], acc[i]);
            }
            float s0,s1,q0,q1; unpack2(sa,s0,s1); unpack2(qa,q0,q1);
            float m    = (s0 + s1) * 0.015625f;
            float varr = fmaf(-m, m, (q0 + q1) * 0.015625f) + LN_EPS;
            float inv  = rsqrtf(varr);
            float stdv = varr * inv;
            float d[7];
            #pragma unroll
            for (int i = 0; i < 7; i++) {
                float a0,a1,ub,su;
                unpack2(acc[i], a0, a1);
                unpack2(Ub[i], ub, su);
                d[i] = fmaf(fmaf(-m, su, a0 + a1), inv, ub);
            }
            float mx = d[0];
            #pragma unroll
            for (int i = 1; i < 7; i++) mx = fmaxf(mx, d[i]);
            float e[7], se = 0.f;
            #pragma unroll
            for (int i = 0; i < 7; i++) { e[i] = __expf(d[i] - mx); se += e[i]; }
            float rinv = 1.0f / se;
            #pragma unroll
            for (int i = 0; i < 7; i++) {
                float w = fmaf(e[i], rinv, EPSA) * inv;
                As[i*257 + tid] = pack2(w, w);
            }
            xrow[32] = pack2(m, stdv);
        }
        __syncthreads();
        // P phase: warp w8 covers tokens [w8*32, w8*32+32), lane = column pair
        {
            int tb = w8 * 32;
            #pragma unroll 4
            for (int j = 0; j < 32; j++) {
                int t = tb + j;
                ull xv = Xs[t*33 + cp];
                #pragma unroll
                for (int i = 0; i < 7; i++) p2[i] = fma2(As[i*257 + t], xv, p2[i]);
            }
        }
        // KD phase: {K,D} += {w,w} * {m,std}
        if (tid < 224) {
            int i = tid >> 5, tg = tid & 31;
            #pragma unroll
            for (int j = 0; j < 8; j++) {
                int t = j*32 + tg;
                kd2 = fma2(As[i*257 + t], Xs[t*33 + 32], kd2);
            }
        }
    }
    __syncthreads();
    #pragma unroll
    for (int i = 0; i < 7; i++) Xs[w8*224 + i*32 + cp] = p2[i];
    ull* redKD = Xs + 2048;
    if (tid < 224) redKD[tid] = kd2;
    __syncthreads();
    if (tid < 224) {
        ull s = 0ull;
        #pragma unroll
        for (int h = 0; h < 8; h++) s = add2(s, Xs[h*224 + tid]);
        g_P2[blk*224 + tid] = s;
    } else if (tid < 231) {
        int i = tid - 224;
        ull s = 0ull;
        #pragma unroll
        for (int tg = 0; tg < 32; tg++) s = add2(s, redKD[i*32 + tg]);
        g_KD2[blk*7 + i] = s;
    }
}

// ---------------------------------------------------------------------------
// slot-side: smem layout (floats)
// ---------------------------------------------------------------------------
#define OA   0
#define OB   12480
#define OP   24960
#define OXA  25408
#define OUPD 25856
#define OH   26304
#define OGI  26752
#define OGH  28096
#define ONEW 29440
#define OFF2 29888
#define OY1  30336
#define OS   31232
#define OQ   31680
#define OU   32128
#define SLOT_SMEM (32576*4)

__device__ __forceinline__ void stageW(float* dst, const float* __restrict__ src,
                                       int rows, int tid) {
    for (int idx = tid; idx < rows*64; idx += 256) {
        int r = idx >> 6, c = idx & 63;
        dst[r*65 + c] = src[idx];
    }
}

__device__ __forceinline__ void warp_ln(const float* src, float* dst,
                                        const float* __restrict__ g,
                                        const float* __restrict__ be,
                                        int w, int lane) {
    float v0 = src[w*64 + lane], v1 = src[w*64 + 32 + lane];
    float s = v0 + v1, ss = v0*v0 + v1*v1;
    #pragma unroll
    for (int o = 16; o; o >>= 1) {
        s  += __shfl_xor_sync(0xffffffffu, s,  o);
        ss += __shfl_xor_sync(0xffffffffu, ss, o);
    }
    float m   = s * 0.015625f;
    float inv = rsqrtf(ss * 0.015625f - m*m + LN_EPS);
    dst[w*64 + lane]      = (v0 - m)*inv*g[lane]      + be[lane];
    dst[w*64 + 32 + lane] = (v1 - m)*inv*g[lane + 32] + be[lane + 32];
}

// prep: cur(smem slots) -> g_ug2, g_ub2
__device__ void do_prep(int b, int tid, float* fs, const float* cur,
                        const float* __restrict__ Wq, const float* __restrict__ bq,
                        const float* __restrict__ Wk, const float* __restrict__ bk,
                        const float* __restrict__ gsl, const float* __restrict__ besl,
                        const float* __restrict__ gin, const float* __restrict__ bein)
{
    float* A = fs + OA; float* B = fs + OB;
    float* sS = fs + OS; float* sQ = fs + OQ; float* sU = fs + OU;
    int w = tid >> 5, lane = tid & 31;
    if (w < 7) warp_ln(cur, sS, gsl, besl, w, lane);
    stageW(A, Wq, 64, tid);
    stageW(B, Wk, 64, tid);
    __syncthreads();
    for (int o = tid; o < 448; o += 256) {
        int i = o >> 6, c = o & 63;
        float a0 = 0.f, a1 = 0.f;
        #pragma unroll 8
        for (int d = 0; d < 64; d += 2) {
            a0 = fmaf(sS[i*64 + d],   A[c*65 + d],   a0);
            a1 = fmaf(sS[i*64 + d+1], A[c*65 + d+1], a1);
        }
        sQ[o] = bq[c] + a0 + a1;
    }
    __syncthreads();
    for (int o = tid; o < 448; o += 256) {
        int i = o >> 6, e = o & 63;
        float a0 = 0.f, a1 = 0.f;
        #pragma unroll 8
        for (int c = 0; c < 64; c += 2) {
            a0 = fmaf(sQ[i*64 + c],   B[c*65 + e],     a0);
            a1 = fmaf(sQ[i*64 + c+1], B[(c+1)*65 + e], a1);
        }
        float u = a0 + a1;
        sU[o] = u;
        ((float*)g_ug2)[b*448 + o] = u * gin[e] * SCALE;
    }
    __syncthreads();
    if (w < 7) {
        float u0 = sU[w*64 + lane], u1 = sU[w*64 + 32 + lane];
        float su = u0*gin[lane]  + u1*gin[lane + 32];
        float ub = u0*bein[lane] + u1*bein[lane + 32]
                 + sQ[w*64 + lane]*bk[lane] + sQ[w*64 + 32 + lane]*bk[lane + 32];
        #pragma unroll
        for (int o = 16; o; o >>= 1) {
            su += __shfl_xor_sync(0xffffffffu, su, o);
            ub += __shfl_xor_sync(0xffffffffu, ub, o);
        }
        if (lane == 0) g_ub2[b*7 + w] = pack2(SCALE*ub, SCALE*su);
    }
}

__global__ void slot_begin(const float* __restrict__ noise, const float* __restrict__ mu,
                           const float* __restrict__ sigma,
                           const float* __restrict__ Wq, const float* __restrict__ bq,
                           const float* __restrict__ Wk, const float* __restrict__ bk,
                           const float* __restrict__ gsl, const float* __restrict__ besl,
                           const float* __restrict__ gin, const float* __restrict__ bein)
{
    extern __shared__ float fs[];
    int b = blockIdx.x, tid = threadIdx.x;
    float* sP = fs + OP;
    for (int idx = tid; idx < 448; idx += 256) {
        int c = idx & 63;
        float v = fmaf(sigma[c], noise[b*448 + idx], mu[c]);
        g_slots[b*448 + idx] = v;
        sP[idx] = v;
    }
    __syncthreads();
    do_prep(b, tid, fs, sP, Wq, bq, Wk, bk, gsl, besl, gin, bein);
}

__global__ void slot_step(const float* __restrict__ Wv, const float* __restrict__ bv,
                          const float* __restrict__ W_ih, const float* __restrict__ W_hh,
                          const float* __restrict__ b_ih, const float* __restrict__ b_hh,
                          const float* __restrict__ W1, const float* __restrict__ b1,
                          const float* __restrict__ W2, const float* __restrict__ b2,
                          const float* __restrict__ gin, const float* __restrict__ bein,
                          const float* __restrict__ gff, const float* __restrict__ beff,
                          const float* __restrict__ Wq, const float* __restrict__ bq,
                          const float* __restrict__ Wk, const float* __restrict__ bk,
                          const float* __restrict__ gsl, const float* __restrict__ besl,
                          float* __restrict__ outp, int doprep)
{
    extern __shared__ float fs[];
    __shared__ float sK[7], sD[7];
    float* A    = fs + OA;
    float* B    = fs + OB;
    float* sP   = fs + OP;
    float* sxa  = fs + OXA;
    float* supd = fs + OUPD;
    float* sh   = fs + OH;
    float* sgi  = fs + OGI;
    float* sgh  = fs + OGH;
    float* snew = fs + ONEW;
    float* sff  = fs + OFF2;
    float* sy1  = fs + OY1;
    int b = blockIdx.x, tid = threadIdx.x;
    int w = tid >> 5, lane = tid & 31;
    const float* gP = (const float*)g_P2;

    // P0
    for (int idx = tid; idx < 448; idx += 256) {
        float s = 0.f;
        #pragma unroll
        for (int ch = 0; ch < 4; ch++) s += gP[(b*4 + ch)*448 + idx];
        sP[idx] = s;
        sh[idx] = g_slots[b*448 + idx];
    }
    if (tid < 7) {
        float K = 0.f, D = 0.f;
        #pragma unroll
        for (int ch = 0; ch < 4; ch++) {
            float k0, d0; unpack2(g_KD2[(b*4 + ch)*7 + tid], k0, d0);
            K += k0; D += d0;
        }
        sK[tid] = K; sD[tid] = D;
    }
    stageW(A, Wv, 64, tid);
    stageW(B, W_ih, 192, tid);
    __syncthreads();
    // P1: xa = (P-K)/D * g_in + be_in
    for (int idx = tid; idx < 448; idx += 256) {
        int e = idx & 63, i = idx >> 6;
        sxa[idx] = fmaf((sP[idx] - sK[i]) / sD[i], gin[e], bein[e]);
    }
    __syncthreads();
    // P2: upd = xa @ Wv^T + bv
    for (int idx = tid; idx < 448; idx += 256) {
        int c = idx & 63, i = idx >> 6;
        float a0 = 0.f, a1 = 0.f;
        #pragma unroll 8
        for (int e = 0; e < 64; e += 2) {
            a0 = fmaf(sxa[i*64 + e],   A[c*65 + e],   a0);
            a1 = fmaf(sxa[i*64 + e+1], A[c*65 + e+1], a1);
        }
        supd[idx] = bv[c] + a0 + a1;
    }
    __syncthreads();
    // P3: gi = upd @ W_ih^T + b_ih ; stage W_hh -> A
    stageW(A, W_hh, 192, tid);
    for (int idx = tid; idx < 1344; idx += 256) {
        int i = idx / 192, r = idx - i*192;
        float a0 = 0.f, a1 = 0.f;
        #pragma unroll 8
        for (int c = 0; c < 64; c += 2) {
            a0 = fmaf(supd[i*64 + c],   B[r*65 + c],   a0);
            a1 = fmaf(supd[i*64 + c+1], B[r*65 + c+1], a1);
        }
        sgi[idx] = b_ih[r] + a0 + a1;
    }
    __syncthreads();
    // P4: gh = h @ W_hh^T + b_hh ; stage W1 -> B
    stageW(B, W1, 128, tid);
    for (int idx = tid; idx < 1344; idx += 256) {
        int i = idx / 192, r = idx - i*192;
        float a0 = 0.f, a1 = 0.f;
        #pragma unroll 8
        for (int c = 0; c < 64; c += 2) {
            a0 = fmaf(sh[i*64 + c],   A[r*65 + c],   a0);
            a1 = fmaf(sh[i*64 + c+1], A[r*65 + c+1], a1);
        }
        sgh[idx] = b_hh[r] + a0 + a1;
    }
    __syncthreads();
    // P5: GRU gates
    for (int idx = tid; idx < 448; idx += 256) {
        int c = idx & 63, i = idx >> 6;
        float rg = 1.0f / (1.0f + __expf(-(sgi[i*192 + c]      + sgh[i*192 + c])));
        float zg = 1.0f / (1.0f + __expf(-(sgi[i*192 + 64 + c] + sgh[i*192 + 64 + c])));
        float ng = tanhf(fmaf(rg, sgh[i*192 + 128 + c], sgi[i*192 + 128 + c]));
        snew[idx] = fmaf(zg, sh[idx] - ng, ng);
    }
    __syncthreads();
    // P6: LN(snew) -> sff ; stage W2 -> A (stride 129)
    if (w < 7) warp_ln(snew, sff, gff, beff, w, lane);
    for (int idx = tid; idx < 8192; idx += 256) {
        int c = idx >> 7, r = idx & 127;
        A[c*129 + r] = W2[idx];
    }
    __syncthreads();
    // P7: y1 = relu(ff @ W1^T + b1)
    for (int idx = tid; idx < 896; idx += 256) {
        int i = idx >> 7, r = idx & 127;
        float a0 = 0.f, a1 = 0.f;
        #pragma unroll 8
        for (int c = 0; c < 64; c += 2) {
            a0 = fmaf(sff[i*64 + c],   B[r*65 + c],   a0);
            a1 = fmaf(sff[i*64 + c+1], B[r*65 + c+1], a1);
        }
        sy1[idx] = fmaxf(b1[r] + a0 + a1, 0.0f);
    }
    __syncthreads();
    // P8: slots = snew + y1 @ W2^T + b2
    for (int idx = tid; idx < 448; idx += 256) {
        int c = idx & 63, i = idx >> 6;
        float a0 = 0.f, a1 = 0.f;
        #pragma unroll 8
        for (int r = 0; r < 128; r += 2) {
            a0 = fmaf(sy1[i*128 + r],   A[c*129 + r],   a0);
            a1 = fmaf(sy1[i*128 + r+1], A[c*129 + r+1], a1);
        }
        float v = snew[idx] + b2[c] + a0 + a1;
        g_slots[b*448 + idx] = v;
        sP[idx] = v;
        if (outp) outp[b*448 + idx] = v;
    }
    if (doprep) {
        __syncthreads();
        do_prep(b, tid, fs, sP, Wq, bq, Wk, bk, gsl, besl, gin, bein);
    }
}

// ---------------------------------------------------------------------------
extern "C" void kernel_launch(void* const* d_in, const int* in_sizes, int n_in,
                              void* d_out, int out_size)
{
    const float* inputs = (const float*)d_in[0];
    const float* noise  = (const float*)d_in[2];
    const float* mu     = (const float*)d_in[3];
    const float* sigma  = (const float*)d_in[4];
    const float* Wq     = (const float*)d_in[5];
    const float* bq     = (const float*)d_in[6];
    const float* Wk     = (const float*)d_in[7];
    const float* bk     = (const float*)d_in[8];
    const float* Wv     = (const float*)d_in[9];
    const float* bv     = (const float*)d_in[10];
    const float* W_ih   = (const float*)d_in[11];
    const float* W_hh   = (const float*)d_in[12];
    const float* b_ih   = (const float*)d_in[13];
    const float* b_hh   = (const float*)d_in[14];
    const float* W1     = (const float*)d_in[15];
    const float* b1     = (const float*)d_in[16];
    const float* W2     = (const float*)d_in[17];
    const float* b2     = (const float*)d_in[18];
    const float* gin    = (const float*)d_in[19];
    const float* bein   = (const float*)d_in[20];
    const float* gsl    = (const float*)d_in[21];
    const float* besl   = (const float*)d_in[22];
    const float* gff    = (const float*)d_in[23];
    const float* beff   = (const float*)d_in[24];

    const int ATTN_SMEM = 10478 * 8;
    static int configured = 0;
    if (!configured) {
        cudaFuncSetAttribute(attn_pass, cudaFuncAttributeMaxDynamicSharedMemorySize, ATTN_SMEM);
        cudaFuncSetAttribute(slot_begin, cudaFuncAttributeMaxDynamicSharedMemorySize, SLOT_SMEM);
        cudaFuncSetAttribute(slot_step, cudaFuncAttributeMaxDynamicSharedMemorySize, SLOT_SMEM);
        configured = 1;
    }

    slot_begin<<<64, 256, SLOT_SMEM>>>(noise, mu, sigma, Wq, bq, Wk, bk,
                                       gsl, besl, gin, bein);
    for (int it = 0; it < 3; it++) {
        attn_pass<<<256, 256, ATTN_SMEM>>>(inputs);
        slot_step<<<64, 256, SLOT_SMEM>>>(Wv, bv, W_ih, W_hh, b_ih, b_hh,
                                          W1, b1, W2, b2, gin, bein, gff, beff,
                                          Wq, bq, Wk, bk, gsl, besl,
                                          it == 2 ? (float*)d_out : nullptr,
                                          it == 2 ? 0 : 1);
    }
}

// round 4
// speedup vs baseline: 3.9978x; 1.1747x over previous
#include <cuda_runtime.h>
#include <math.h>
typedef unsigned long long ull;

#define SCALE 0.125f
#define EPSA 1e-8f
#define LN_EPS 1e-5f

__device__ __forceinline__ ull fma2(ull a, ull b, ull c){ull d;asm("fma.rn.f32x2 %0,%1,%2,%3;":"=l"(d):"l"(a),"l"(b),"l"(c));return d;}
__device__ __forceinline__ ull add2(ull a, ull b){ull d;asm("add.rn.f32x2 %0,%1,%2;":"=l"(d):"l"(a),"l"(b));return d;}
__device__ __forceinline__ ull pack2(float lo, float hi){ull d;asm("mov.b64 %0,{%1,%2};":"=l"(d):"f"(lo),"f"(hi));return d;}
__device__ __forceinline__ void unpack2(ull v, float& lo, float& hi){asm("mov.b64 {%0,%1},%2;":"=f"(lo),"=f"(hi):"l"(v));}

// device scratch
__device__ float g_slots[64*448];
__device__ ull   g_ug2[64*224];     // pairs of SCALE*u*g_in
__device__ ull   g_ub2[64*7];       // {ub, Su}
__device__ ull   g_P2[1024*224];    // per (b,chunk16) raw-x weighted sums
__device__ ull   g_KD2[1024*7];     // per (b,chunk16) {K, D}

// ---------------------------------------------------------------------------
// attn_pass: grid 1024 = 64 batches x 16 chunks of 256 tokens (2 passes x 128)
// CTA = 128 threads, 4 CTAs/SM.
// ---------------------------------------------------------------------------
__global__ void __launch_bounds__(128,4) attn_pass(const float* __restrict__ inp)
{
    extern __shared__ ull sm[];
    ull* Xs = sm;            // [128][33]: 32 raw-x pairs + {m,std}
    ull* As = sm + 4224;     // [7][129] packed {w,w}
    ull* Ub = sm + 5127;     // [7] {ub,Su}
    ull* Ug = sm + 5134;     // [7][32]

    int tid = threadIdx.x, blk = blockIdx.x;
    int b = blk >> 4, chunk = blk & 15;

    for (int i = tid; i < 224; i += 128) Ug[i] = g_ug2[b*224 + i];
    if (tid < 7) Ub[tid] = g_ub2[b*7 + tid];

    ull p2[7]; ull kd2 = 0ull;
    #pragma unroll
    for (int i = 0; i < 7; i++) p2[i] = 0ull;

    const ulonglong2* in4 = (const ulonglong2*)inp + (size_t)(b*4096 + chunk*256)*16;
    int w8 = tid >> 5, cp = tid & 31;

    for (int pass = 0; pass < 2; pass++) {
        __syncthreads();
        const ulonglong2* src = in4 + pass*128*16;
        #pragma unroll
        for (int k = 0; k < 16; k++) {
            int idx = tid + k*128;
            int t = idx >> 4, c = idx & 15;
            ulonglong2 v = src[idx];
            Xs[t*33 + c*2]     = v.x;
            Xs[t*33 + c*2 + 1] = v.y;
        }
        __syncthreads();
        // token phase: thread t = tid handles token t
        {
            ull* xrow = Xs + tid*33;
            ull sa = 0ull, qa = 0ull, acc[7];
            #pragma unroll
            for (int i = 0; i < 7; i++) acc[i] = 0ull;
            #pragma unroll
            for (int q = 0; q < 32; q++) {
                ull xv = xrow[q];
                sa = add2(sa, xv);
                qa = fma2(xv, xv, qa);
                #pragma unroll
                for (int i = 0; i < 7; i++) acc[i] = fma2(xv, Ug[i*32 + q], acc[i]);
            }
            float s0,s1,q0,q1; unpack2(sa,s0,s1); unpack2(qa,q0,q1);
            float m    = (s0 + s1) * 0.015625f;
            float varr = fmaf(-m, m, (q0 + q1) * 0.015625f) + LN_EPS;
            float inv  = rsqrtf(varr);
            float stdv = varr * inv;
            float d[7];
            #pragma unroll
            for (int i = 0; i < 7; i++) {
                float a0,a1,ub,su;
                unpack2(acc[i], a0, a1);
                unpack2(Ub[i], ub, su);
                d[i] = fmaf(fmaf(-m, su, a0 + a1), inv, ub);
            }
            float mx = d[0];
            #pragma unroll
            for (int i = 1; i < 7; i++) mx = fmaxf(mx, d[i]);
            float e[7], se = 0.f;
            #pragma unroll
            for (int i = 0; i < 7; i++) { e[i] = __expf(d[i] - mx); se += e[i]; }
            float rinv = 1.0f / se;
            #pragma unroll
            for (int i = 0; i < 7; i++) {
                float w = fmaf(e[i], rinv, EPSA) * inv;
                As[i*129 + tid] = pack2(w, w);
            }
            xrow[32] = pack2(m, stdv);
        }
        __syncthreads();
        // P phase: warp w8 covers tokens [w8*32, w8*32+32), lane = column pair
        {
            int tb = w8 * 32;
            #pragma unroll 4
            for (int j = 0; j < 32; j++) {
                int t = tb + j;
                ull xv = Xs[t*33 + cp];
                #pragma unroll
                for (int i = 0; i < 7; i++) p2[i] = fma2(As[i*129 + t], xv, p2[i]);
            }
        }
        // KD phase: {K,D} += {w,w} * {m,std}
        if (tid < 112) {
            int i = tid >> 4, tg = tid & 15;
            #pragma unroll
            for (int j = 0; j < 8; j++) {
                int t = j*16 + tg;
                kd2 = fma2(As[i*129 + t], Xs[t*33 + 32], kd2);
            }
        }
    }
    __syncthreads();
    #pragma unroll
    for (int i = 0; i < 7; i++) Xs[w8*224 + i*32 + cp] = p2[i];
    ull* redKD = Xs + 896;
    if (tid < 112) redKD[tid] = kd2;
    __syncthreads();
    for (int o = tid; o < 224; o += 128) {
        ull s = 0ull;
        #pragma unroll
        for (int h = 0; h < 4; h++) s = add2(s, Xs[h*224 + o]);
        g_P2[blk*224 + o] = s;
    }
    if (tid >= 112 && tid < 119) {
        int i = tid - 112;
        ull s = 0ull;
        #pragma unroll
        for (int tg = 0; tg < 16; tg++) s = add2(s, redKD[i*16 + tg]);
        g_KD2[blk*7 + i] = s;
    }
}

// ---------------------------------------------------------------------------
// slot-side: all weights smem-resident. smem layout (float offsets):
// ---------------------------------------------------------------------------
#define OWQ   0
#define OWK   4160
#define OWV   8320
#define OWIH  12480
#define OWHH  24960
#define OW1   37440
#define OW2   45760
#define OXA   54016   // sxa / sff / prep-sS
#define OUPD  54464   // supd / prep-sQ
#define OH    54912   // h (old slots) / new slots for prep
#define ONEW  55360
#define OY1   55808   // y1(896) / prep-sU(448)
#define SLOT_SMEM ((56704)*4)

__device__ __forceinline__ void stage65(float* dst, const float* __restrict__ src,
                                        int rows, int tid) {
    int n4 = rows*16;
    for (int i = tid; i < n4; i += 256) {
        float4 v = ((const float4*)src)[i];
        int r = i >> 4, c = (i & 15)*4;
        float* d = dst + r*65 + c;
        d[0]=v.x; d[1]=v.y; d[2]=v.z; d[3]=v.w;
    }
}
__device__ __forceinline__ void stage129(float* dst, const float* __restrict__ src,
                                         int rows, int tid) {
    int n4 = rows*32;
    for (int i = tid; i < n4; i += 256) {
        float4 v = ((const float4*)src)[i];
        int r = i >> 5, c = (i & 31)*4;
        float* d = dst + r*129 + c;
        d[0]=v.x; d[1]=v.y; d[2]=v.z; d[3]=v.w;
    }
}

__device__ __forceinline__ void warp_ln(const float* src, float* dst,
                                        const float* __restrict__ g,
                                        const float* __restrict__ be,
                                        int w, int lane) {
    float v0 = src[w*64 + lane], v1 = src[w*64 + 32 + lane];
    float s = v0 + v1, ss = v0*v0 + v1*v1;
    #pragma unroll
    for (int o = 16; o; o >>= 1) {
        s  += __shfl_xor_sync(0xffffffffu, s,  o);
        ss += __shfl_xor_sync(0xffffffffu, ss, o);
    }
    float m   = s * 0.015625f;
    float inv = rsqrtf(ss * 0.015625f - m*m + LN_EPS);
    dst[w*64 + lane]      = (v0 - m)*inv*g[lane]      + be[lane];
    dst[w*64 + 32 + lane] = (v1 - m)*inv*g[lane + 32] + be[lane + 32];
}

// prep: slots in fs[OH] -> g_ug2, g_ub2. Requires OWQ/OWK staged.
__device__ void do_prep(int b, int tid, float* fs,
                        const float* __restrict__ bq, const float* __restrict__ bk,
                        const float* __restrict__ gsl, const float* __restrict__ besl,
                        const float* __restrict__ gin, const float* __restrict__ bein)
{
    float* sS = fs + OXA;
    float* sQ = fs + OUPD;
    float* sU = fs + OY1;
    int w = tid >> 5, lane = tid & 31;
    if (w < 7) warp_ln(fs + OH, sS, gsl, besl, w, lane);
    __syncthreads();
    for (int o = tid; o < 448; o += 256) {
        int i = o >> 6, c = o & 63;
        float a0 = 0.f, a1 = 0.f;
        #pragma unroll 8
        for (int d = 0; d < 64; d += 2) {
            a0 = fmaf(sS[i*64 + d],   fs[OWQ + c*65 + d],   a0);
            a1 = fmaf(sS[i*64 + d+1], fs[OWQ + c*65 + d+1], a1);
        }
        sQ[o] = bq[c] + a0 + a1;
    }
    __syncthreads();
    for (int o = tid; o < 448; o += 256) {
        int i = o >> 6, e = o & 63;
        float a0 = 0.f, a1 = 0.f;
        #pragma unroll 8
        for (int c = 0; c < 64; c += 2) {
            a0 = fmaf(sQ[i*64 + c],   fs[OWK + c*65 + e],     a0);
            a1 = fmaf(sQ[i*64 + c+1], fs[OWK + (c+1)*65 + e], a1);
        }
        float u = a0 + a1;
        sU[o] = u;
        ((float*)g_ug2)[b*448 + o] = u * gin[e] * SCALE;
    }
    __syncthreads();
    if (w < 7) {
        float u0 = sU[w*64 + lane], u1 = sU[w*64 + 32 + lane];
        float su = u0*gin[lane]  + u1*gin[lane + 32];
        float ub = u0*bein[lane] + u1*bein[lane + 32]
                 + sQ[w*64 + lane]*bk[lane] + sQ[w*64 + 32 + lane]*bk[lane + 32];
        #pragma unroll
        for (int o = 16; o; o >>= 1) {
            su += __shfl_xor_sync(0xffffffffu, su, o);
            ub += __shfl_xor_sync(0xffffffffu, ub, o);
        }
        if (lane == 0) g_ub2[b*7 + w] = pack2(SCALE*ub, SCALE*su);
    }
}

__global__ void slot_begin(const float* __restrict__ noise, const float* __restrict__ mu,
                           const float* __restrict__ sigma,
                           const float* __restrict__ Wq, const float* __restrict__ bq,
                           const float* __restrict__ Wk, const float* __restrict__ bk,
                           const float* __restrict__ gsl, const float* __restrict__ besl,
                           const float* __restrict__ gin, const float* __restrict__ bein)
{
    extern __shared__ float fs[];
    int b = blockIdx.x, tid = threadIdx.x;
    stage65(fs + OWQ, Wq, 64, tid);
    stage65(fs + OWK, Wk, 64, tid);
    for (int idx = tid; idx < 448; idx += 256) {
        int c = idx & 63;
        float v = fmaf(sigma[c], noise[b*448 + idx], mu[c]);
        g_slots[b*448 + idx] = v;
        fs[OH + idx] = v;
    }
    __syncthreads();
    do_prep(b, tid, fs, bq, bk, gsl, besl, gin, bein);
}

__global__ void slot_step(const float* __restrict__ Wv, const float* __restrict__ bv,
                          const float* __restrict__ W_ih, const float* __restrict__ W_hh,
                          const float* __restrict__ b_ih, const float* __restrict__ b_hh,
                          const float* __restrict__ W1, const float* __restrict__ b1,
                          const float* __restrict__ W2, const float* __restrict__ b2,
                          const float* __restrict__ gin, const float* __restrict__ bein,
                          const float* __restrict__ gff, const float* __restrict__ beff,
                          const float* __restrict__ Wq, const float* __restrict__ bq,
                          const float* __restrict__ Wk, const float* __restrict__ bk,
                          const float* __restrict__ gsl, const float* __restrict__ besl,
                          float* __restrict__ outp, int doprep)
{
    extern __shared__ float fs[];
    __shared__ float sK[7], sD[7];
    float* sxa  = fs + OXA;
    float* supd = fs + OUPD;
    float* sh   = fs + OH;
    float* snew = fs + ONEW;
    float* sff  = fs + OXA;   // overlays sxa (dead after P2)
    float* sy1  = fs + OY1;
    int b = blockIdx.x, tid = threadIdx.x;
    int w = tid >> 5, lane = tid & 31;
    const float* gP = (const float*)g_P2;

    // stage all weights (float4 coalesced)
    stage65 (fs + OWV,  Wv,   64, tid);
    stage65 (fs + OWIH, W_ih, 192, tid);
    stage65 (fs + OWHH, W_hh, 192, tid);
    stage65 (fs + OW1,  W1,  128, tid);
    stage129(fs + OW2,  W2,   64, tid);
    if (doprep) {
        stage65(fs + OWQ, Wq, 64, tid);
        stage65(fs + OWK, Wk, 64, tid);
    }

    // P0: reduce partials (16 chunks), load old slots
    for (int idx = tid; idx < 448; idx += 256) {
        float s = 0.f;
        #pragma unroll
        for (int ch = 0; ch < 16; ch++) s += gP[(b*16 + ch)*448 + idx];
        sxa[idx] = s;          // raw P for now
        sh[idx]  = g_slots[b*448 + idx];
    }
    if (tid < 7) {
        float K = 0.f, D = 0.f;
        #pragma unroll
        for (int ch = 0; ch < 16; ch++) {
            float k0, d0; unpack2(g_KD2[(b*16 + ch)*7 + tid], k0, d0);
            K += k0; D += d0;
        }
        sK[tid] = K; sD[tid] = D;
    }
    __syncthreads();
    // P1: xa = (P-K)/D * g_in + be_in  (in place)
    for (int idx = tid; idx < 448; idx += 256) {
        int e = idx & 63, i = idx >> 6;
        sxa[idx] = fmaf((sxa[idx] - sK[i]) / sD[i], gin[e], bein[e]);
    }
    __syncthreads();
    // P2: upd = xa @ Wv^T + bv
    for (int idx = tid; idx < 448; idx += 256) {
        int c = idx & 63, i = idx >> 6;
        float a0 = 0.f, a1 = 0.f;
        #pragma unroll 8
        for (int e = 0; e < 64; e += 2) {
            a0 = fmaf(sxa[i*64 + e],   fs[OWV + c*65 + e],   a0);
            a1 = fmaf(sxa[i*64 + e+1], fs[OWV + c*65 + e+1], a1);
        }
        supd[idx] = bv[c] + a0 + a1;
    }
    __syncthreads();
    // P3: fused GRU: 6 dots + gates per (i,c)
    for (int idx = tid; idx < 448; idx += 256) {
        int c = idx & 63, i = idx >> 6;
        const float* wir = fs + OWIH + c*65;
        const float* wiz = fs + OWIH + (64 + c)*65;
        const float* win = fs + OWIH + (128 + c)*65;
        const float* whr = fs + OWHH + c*65;
        const float* whz = fs + OWHH + (64 + c)*65;
        const float* whn = fs + OWHH + (128 + c)*65;
        const float* xu = supd + i*64;
        const float* hh = sh + i*64;
        float gir = 0.f, giz = 0.f, gin_ = 0.f, ghr = 0.f, ghz = 0.f, ghn = 0.f;
        #pragma unroll 8
        for (int d = 0; d < 64; d++) {
            float xv = xu[d], hv = hh[d];
            gir = fmaf(xv, wir[d], gir);
            giz = fmaf(xv, wiz[d], giz);
            gin_ = fmaf(xv, win[d], gin_);
            ghr = fmaf(hv, whr[d], ghr);
            ghz = fmaf(hv, whz[d], ghz);
            ghn = fmaf(hv, whn[d], ghn);
        }
        gir += b_ih[c];       ghr += b_hh[c];
        giz += b_ih[64 + c];  ghz += b_hh[64 + c];
        gin_ += b_ih[128 + c]; ghn += b_hh[128 + c];
        float rg = 1.0f / (1.0f + __expf(-(gir + ghr)));
        float zg = 1.0f / (1.0f + __expf(-(giz + ghz)));
        float ng = tanhf(fmaf(rg, ghn, gin_));
        snew[idx] = fmaf(zg, sh[idx] - ng, ng);
    }
    __syncthreads();
    // P4: LN(snew) -> sff (overlays sxa)
    if (w < 7) warp_ln(snew, sff, gff, beff, w, lane);
    __syncthreads();
    // P5: y1 = relu(ff @ W1^T + b1)
    for (int idx = tid; idx < 896; idx += 256) {
        int i = idx >> 7, r = idx & 127;
        float a0 = 0.f, a1 = 0.f;
        #pragma unroll 8
        for (int c = 0; c < 64; c += 2) {
            a0 = fmaf(sff[i*64 + c],   fs[OW1 + r*65 + c],   a0);
            a1 = fmaf(sff[i*64 + c+1], fs[OW1 + r*65 + c+1], a1);
        }
        sy1[idx] = fmaxf(b1[r] + a0 + a1, 0.0f);
    }
    __syncthreads();
    // P6: slots = snew + y1 @ W2^T + b2 -> sh (input to prep)
    for (int idx = tid; idx < 448; idx += 256) {
        int c = idx & 63, i = idx >> 6;
        float a0 = 0.f, a1 = 0.f;
        #pragma unroll 8
        for (int r = 0; r < 128; r += 2) {
            a0 = fmaf(sy1[i*128 + r],   fs[OW2 + c*129 + r],   a0);
            a1 = fmaf(sy1[i*128 + r+1], fs[OW2 + c*129 + r+1], a1);
        }
        float v = snew[idx] + b2[c] + a0 + a1;
        g_slots[b*448 + idx] = v;
        sh[idx] = v;
        if (outp) outp[b*448 + idx] = v;
    }
    if (doprep) {
        __syncthreads();
        do_prep(b, tid, fs, bq, bk, gsl, besl, gin, bein);
    }
}

// ---------------------------------------------------------------------------
extern "C" void kernel_launch(void* const* d_in, const int* in_sizes, int n_in,
                              void* d_out, int out_size)
{
    const float* inputs = (const float*)d_in[0];
    const float* noise  = (const float*)d_in[2];
    const float* mu     = (const float*)d_in[3];
    const float* sigma  = (const float*)d_in[4];
    const float* Wq     = (const float*)d_in[5];
    const float* bq     = (const float*)d_in[6];
    const float* Wk     = (const float*)d_in[7];
    const float* bk     = (const float*)d_in[8];
    const float* Wv     = (const float*)d_in[9];
    const float* bv     = (const float*)d_in[10];
    const float* W_ih   = (const float*)d_in[11];
    const float* W_hh   = (const float*)d_in[12];
    const float* b_ih   = (const float*)d_in[13];
    const float* b_hh   = (const float*)d_in[14];
    const float* W1     = (const float*)d_in[15];
    const float* b1     = (const float*)d_in[16];
    const float* W2     = (const float*)d_in[17];
    const float* b2     = (const float*)d_in[18];
    const float* gin    = (const float*)d_in[19];
    const float* bein   = (const float*)d_in[20];
    const float* gsl    = (const float*)d_in[21];
    const float* besl   = (const float*)d_in[22];
    const float* gff    = (const float*)d_in[23];
    const float* beff   = (const float*)d_in[24];

    const int ATTN_SMEM = 5358 * 8;
    static int configured = 0;
    if (!configured) {
        cudaFuncSetAttribute(attn_pass, cudaFuncAttributeMaxDynamicSharedMemorySize, ATTN_SMEM);
        cudaFuncSetAttribute(slot_begin, cudaFuncAttributeMaxDynamicSharedMemorySize, SLOT_SMEM);
        cudaFuncSetAttribute(slot_step, cudaFuncAttributeMaxDynamicSharedMemorySize, SLOT_SMEM);
        configured = 1;
    }

    slot_begin<<<64, 256, SLOT_SMEM>>>(noise, mu, sigma, Wq, bq, Wk, bk,
                                       gsl, besl, gin, bein);
    for (int it = 0; it < 3; it++) {
        attn_pass<<<1024, 128, ATTN_SMEM>>>(inputs);
        slot_step<<<64, 256, SLOT_SMEM>>>(Wv, bv, W_ih, W_hh, b_ih, b_hh,
                                          W1, b1, W2, b2, gin, bein, gff, beff,
                                          Wq, bq, Wk, bk, gsl, besl,
                                          it == 2 ? (float*)d_out : nullptr,
                                          it == 2 ? 0 : 1);
    }
}

// round 6
// speedup vs baseline: 4.7276x; 1.1825x over previous
#include <cuda_runtime.h>
#include <math.h>
typedef unsigned long long ull;

#define SCALE 0.125f
#define EPSA 1e-8f
#define LN_EPS 1e-5f

__device__ __forceinline__ ull fma2(ull a, ull b, ull c){ull d;asm("fma.rn.f32x2 %0,%1,%2,%3;":"=l"(d):"l"(a),"l"(b),"l"(c));return d;}
__device__ __forceinline__ ull add2(ull a, ull b){ull d;asm("add.rn.f32x2 %0,%1,%2;":"=l"(d):"l"(a),"l"(b));return d;}
__device__ __forceinline__ ull pack2(float lo, float hi){ull d;asm("mov.b64 %0,{%1,%2};":"=l"(d):"f"(lo),"f"(hi));return d;}
__device__ __forceinline__ void unpack2(ull v, float& lo, float& hi){asm("mov.b64 {%0,%1},%2;":"=f"(lo),"=f"(hi):"l"(v));}

// device scratch
__device__ float g_slots[64*448];
__device__ ull   g_ug2[64*224];     // pairs of SCALE*u*g_in
__device__ ull   g_ub2[64*7];       // {ub, Su}
__device__ ull   g_P2[1024*224];    // per (b,chunk16) raw-x weighted sums
__device__ ull   g_KD2[1024*7];     // per (b,chunk16) {K, D}

// ---------------------------------------------------------------------------
// attn_pass: grid 1024 = 64 batches x 16 chunks of 256 tokens (2 passes x 128)
// CTA = 128 threads, 4 CTAs/SM. Xs rows stride 34 ull (128-bit aligned,
// conflict-free for LDS.128); As transposed [token][10] for vector broadcast.
// ---------------------------------------------------------------------------
__global__ void __launch_bounds__(128,4) attn_pass(const float* __restrict__ inp)
{
    extern __shared__ ull sm[];
    ull* Xs = sm;            // [128][34]: 32 raw-x pairs + {m,std} @32 + pad
    ull* As = sm + 4352;     // [128][10]: 7 packed {w,w} + pad
    ull* Ub = sm + 5632;     // [7] {ub,Su} (+1 pad)
    ull* Ug = sm + 5640;     // [7][32]

    int tid = threadIdx.x, blk = blockIdx.x;
    int b = blk >> 4, chunk = blk & 15;

    for (int i = tid; i < 224; i += 128) Ug[i] = g_ug2[b*224 + i];
    if (tid < 7) Ub[tid] = g_ub2[b*7 + tid];

    ull p2[7]; ull kd2 = 0ull;
    #pragma unroll
    for (int i = 0; i < 7; i++) p2[i] = 0ull;

    const ulonglong2* in4 = (const ulonglong2*)inp + (size_t)(b*4096 + chunk*256)*16;
    int w8 = tid >> 5, cp = tid & 31;

    for (int pass = 0; pass < 2; pass++) {
        __syncthreads();
        const ulonglong2* src = in4 + pass*128*16;
        #pragma unroll
        for (int k = 0; k < 16; k++) {
            int idx = tid + k*128;
            int t = idx >> 4, c = idx & 15;
            ulonglong2 v = src[idx];
            *reinterpret_cast<ulonglong2*>(Xs + t*34 + c*2) = v;
        }
        __syncthreads();
        // ---- token phase: thread t = tid handles token t ----
        {
            ull* xrow = Xs + tid*34;
            ull sa = 0ull, qa = 0ull, acc[7];
            #pragma unroll
            for (int i = 0; i < 7; i++) acc[i] = 0ull;
            #pragma unroll
            for (int q2 = 0; q2 < 16; q2++) {
                ulonglong2 xv = *reinterpret_cast<const ulonglong2*>(xrow + q2*2);
                sa = add2(add2(sa, xv.x), xv.y);
                qa = fma2(xv.y, xv.y, fma2(xv.x, xv.x, qa));
                #pragma unroll
                for (int i = 0; i < 7; i++) {
                    ulonglong2 u = *reinterpret_cast<const ulonglong2*>(Ug + i*32 + q2*2);
                    acc[i] = fma2(xv.y, u.y, fma2(xv.x, u.x, acc[i]));
                }
            }
            float s0,s1,q0,q1; unpack2(sa,s0,s1); unpack2(qa,q0,q1);
            float m    = (s0 + s1) * 0.015625f;
            float varr = fmaf(-m, m, (q0 + q1) * 0.015625f) + LN_EPS;
            float inv  = rsqrtf(varr);
            float stdv = varr * inv;
            float d[7];
            #pragma unroll
            for (int i = 0; i < 7; i++) {
                float a0,a1,ub,su;
                unpack2(acc[i], a0, a1);
                unpack2(Ub[i], ub, su);
                d[i] = fmaf(fmaf(-m, su, a0 + a1), inv, ub);
            }
            float mx = d[0];
            #pragma unroll
            for (int i = 1; i < 7; i++) mx = fmaxf(mx, d[i]);
            float e[7], se = 0.f;
            #pragma unroll
            for (int i = 0; i < 7; i++) { e[i] = __expf(d[i] - mx); se += e[i]; }
            float rinv = 1.0f / se;
            float wv[7];
            #pragma unroll
            for (int i = 0; i < 7; i++) wv[i] = fmaf(e[i], rinv, EPSA) * inv;
            ull* arow = As + tid*10;
            *reinterpret_cast<ulonglong2*>(arow + 0) =
                make_ulonglong2(pack2(wv[0],wv[0]), pack2(wv[1],wv[1]));
            *reinterpret_cast<ulonglong2*>(arow + 2) =
                make_ulonglong2(pack2(wv[2],wv[2]), pack2(wv[3],wv[3]));
            *reinterpret_cast<ulonglong2*>(arow + 4) =
                make_ulonglong2(pack2(wv[4],wv[4]), pack2(wv[5],wv[5]));
            *reinterpret_cast<ulonglong2*>(arow + 6) =
                make_ulonglong2(pack2(wv[6],wv[6]), pack2(wv[6],wv[6]));
            xrow[32] = pack2(m, stdv);
        }
        __syncthreads();
        // ---- P phase: warp w8 covers tokens [w8*32, +32), lane = column pair ----
        {
            int tb = w8 * 32;
            #pragma unroll 4
            for (int j = 0; j < 32; j++) {
                int t = tb + j;
                ull xv = Xs[t*34 + cp];
                const ulonglong2* ap = reinterpret_cast<const ulonglong2*>(As + t*10);
                ulonglong2 a01 = ap[0], a23 = ap[1], a45 = ap[2];
                ull a6 = As[t*10 + 6];
                p2[0] = fma2(a01.x, xv, p2[0]);
                p2[1] = fma2(a01.y, xv, p2[1]);
                p2[2] = fma2(a23.x, xv, p2[2]);
                p2[3] = fma2(a23.y, xv, p2[3]);
                p2[4] = fma2(a45.x, xv, p2[4]);
                p2[5] = fma2(a45.y, xv, p2[5]);
                p2[6] = fma2(a6,    xv, p2[6]);
            }
        }
        // ---- KD phase: {K,D} += {w,w} * {m,std} ----
        if (tid < 112) {
            int i = tid >> 4, tg = tid & 15;
            #pragma unroll
            for (int j = 0; j < 8; j++) {
                int t = j*16 + tg;
                kd2 = fma2(As[t*10 + i], Xs[t*34 + 32], kd2);
            }
        }
    }
    __syncthreads();
    #pragma unroll
    for (int i = 0; i < 7; i++) Xs[w8*224 + i*32 + cp] = p2[i];
    ull* redKD = Xs + 896;
    if (tid < 112) redKD[tid] = kd2;
    __syncthreads();
    for (int o = tid; o < 224; o += 128) {
        ull s = 0ull;
        #pragma unroll
        for (int h = 0; h < 4; h++) s = add2(s, Xs[h*224 + o]);
        g_P2[blk*224 + o] = s;
    }
    if (tid >= 112 && tid < 119) {
        int i = tid - 112;
        ull s = 0ull;
        #pragma unroll
        for (int tg = 0; tg < 16; tg++) s = add2(s, redKD[i*16 + tg]);
        g_KD2[blk*7 + i] = s;
    }
}

// ---------------------------------------------------------------------------
// slot-side: all weights smem-resident, 512 threads. smem (float offsets):
// ---------------------------------------------------------------------------
#define OWQ   0
#define OWK   4160
#define OWV   8320
#define OWIH  12480
#define OWHH  24960
#define OW1   37440
#define OW2   45760
#define OXA   54016   // sxa / sff / prep-sS
#define OUPD  54464   // supd / prep-sQ
#define OH    54912   // h (old slots) / new slots for prep
#define ONEW  55360
#define OY1   55808   // y1(896) / prep-sU(448)
#define SLOT_SMEM ((56704)*4)

__device__ __forceinline__ void stage65(float* dst, const float* __restrict__ src,
                                        int rows, int tid, int nt) {
    int n4 = rows*16;
    for (int i = tid; i < n4; i += nt) {
        float4 v = ((const float4*)src)[i];
        int r = i >> 4, c = (i & 15)*4;
        float* d = dst + r*65 + c;
        d[0]=v.x; d[1]=v.y; d[2]=v.z; d[3]=v.w;
    }
}
__device__ __forceinline__ void stage129(float* dst, const float* __restrict__ src,
                                         int rows, int tid, int nt) {
    int n4 = rows*32;
    for (int i = tid; i < n4; i += nt) {
        float4 v = ((const float4*)src)[i];
        int r = i >> 5, c = (i & 31)*4;
        float* d = dst + r*129 + c;
        d[0]=v.x; d[1]=v.y; d[2]=v.z; d[3]=v.w;
    }
}

__device__ __forceinline__ void warp_ln(const float* src, float* dst,
                                        const float* __restrict__ g,
                                        const float* __restrict__ be,
                                        int w, int lane) {
    float v0 = src[w*64 + lane], v1 = src[w*64 + 32 + lane];
    float s = v0 + v1, ss = v0*v0 + v1*v1;
    #pragma unroll
    for (int o = 16; o; o >>= 1) {
        s  += __shfl_xor_sync(0xffffffffu, s,  o);
        ss += __shfl_xor_sync(0xffffffffu, ss, o);
    }
    float m   = s * 0.015625f;
    float inv = rsqrtf(ss * 0.015625f - m*m + LN_EPS);
    dst[w*64 + lane]      = (v0 - m)*inv*g[lane]      + be[lane];
    dst[w*64 + 32 + lane] = (v1 - m)*inv*g[lane + 32] + be[lane + 32];
}

// prep: slots in fs[OH] -> g_ug2, g_ub2. Requires OWQ/OWK staged.
__device__ void do_prep(int b, int tid, float* fs,
                        const float* __restrict__ bq, const float* __restrict__ bk,
                        const float* __restrict__ gsl, const float* __restrict__ besl,
                        const float* __restrict__ gin, const float* __restrict__ bein)
{
    float* sS = fs + OXA;
    float* sQ = fs + OUPD;
    float* sU = fs + OY1;
    int w = tid >> 5, lane = tid & 31;
    if (w < 7) warp_ln(fs + OH, sS, gsl, besl, w, lane);
    __syncthreads();
    if (tid < 448) {
        int i = tid >> 6, c = tid & 63;
        float a0 = 0.f, a1 = 0.f;
        #pragma unroll 8
        for (int d = 0; d < 64; d += 2) {
            a0 = fmaf(sS[i*64 + d],   fs[OWQ + c*65 + d],   a0);
            a1 = fmaf(sS[i*64 + d+1], fs[OWQ + c*65 + d+1], a1);
        }
        sQ[tid] = bq[c] + a0 + a1;
    }
    __syncthreads();
    if (tid < 448) {
        int i = tid >> 6, e = tid & 63;
        float a0 = 0.f, a1 = 0.f;
        #pragma unroll 8
        for (int c = 0; c < 64; c += 2) {
            a0 = fmaf(sQ[i*64 + c],   fs[OWK + c*65 + e],     a0);
            a1 = fmaf(sQ[i*64 + c+1], fs[OWK + (c+1)*65 + e], a1);
        }
        float u = a0 + a1;
        sU[tid] = u;
        ((float*)g_ug2)[b*448 + tid] = u * gin[e] * SCALE;
    }
    __syncthreads();
    if (w < 7) {
        float u0 = sU[w*64 + lane], u1 = sU[w*64 + 32 + lane];
        float su = u0*gin[lane]  + u1*gin[lane + 32];
        float ub = u0*bein[lane] + u1*bein[lane + 32]
                 + sQ[w*64 + lane]*bk[lane] + sQ[w*64 + 32 + lane]*bk[lane + 32];
        #pragma unroll
        for (int o = 16; o; o >>= 1) {
            su += __shfl_xor_sync(0xffffffffu, su, o);
            ub += __shfl_xor_sync(0xffffffffu, ub, o);
        }
        if (lane == 0) g_ub2[b*7 + w] = pack2(SCALE*ub, SCALE*su);
    }
}

__global__ void __launch_bounds__(512,1)
slot_begin(const float* __restrict__ noise, const float* __restrict__ mu,
           const float* __restrict__ sigma,
           const float* __restrict__ Wq, const float* __restrict__ bq,
           const float* __restrict__ Wk, const float* __restrict__ bk,
           const float* __restrict__ gsl, const float* __restrict__ besl,
           const float* __restrict__ gin, const float* __restrict__ bein)
{
    extern __shared__ float fs[];
    int b = blockIdx.x, tid = threadIdx.x;
    stage65(fs + OWQ, Wq, 64, tid, 512);
    stage65(fs + OWK, Wk, 64, tid, 512);
    if (tid < 448) {
        int c = tid & 63;
        float v = fmaf(sigma[c], noise[b*448 + tid], mu[c]);
        g_slots[b*448 + tid] = v;
        fs[OH + tid] = v;
    }
    __syncthreads();
    do_prep(b, tid, fs, bq, bk, gsl, besl, gin, bein);
}

__global__ void __launch_bounds__(512,1)
slot_step(const float* __restrict__ Wv, const float* __restrict__ bv,
          const float* __restrict__ W_ih, const float* __restrict__ W_hh,
          const float* __restrict__ b_ih, const float* __restrict__ b_hh,
          const float* __restrict__ W1, const float* __restrict__ b1,
          const float* __restrict__ W2, const float* __restrict__ b2,
          const float* __restrict__ gin, const float* __restrict__ bein,
          const float* __restrict__ gff, const float* __restrict__ beff,
          const float* __restrict__ Wq, const float* __restrict__ bq,
          const float* __restrict__ Wk, const float* __restrict__ bk,
          const float* __restrict__ gsl, const float* __restrict__ besl,
          float* __restrict__ outp, int doprep)
{
    extern __shared__ float fs[];
    __shared__ float sK[7], sD[7];
    float* sxa  = fs + OXA;
    float* supd = fs + OUPD;
    float* sh   = fs + OH;
    float* snew = fs + ONEW;
    float* sff  = fs + OXA;   // overlays sxa (dead after P2)
    float* sy1  = fs + OY1;
    int b = blockIdx.x, tid = threadIdx.x;
    int w = tid >> 5, lane = tid & 31;
    const float* gP = (const float*)g_P2;

    // stage all weights (float4 coalesced)
    stage65 (fs + OWV,  Wv,   64, tid, 512);
    stage65 (fs + OWIH, W_ih, 192, tid, 512);
    stage65 (fs + OWHH, W_hh, 192, tid, 512);
    stage65 (fs + OW1,  W1,  128, tid, 512);
    stage129(fs + OW2,  W2,   64, tid, 512);
    if (doprep) {
        stage65(fs + OWQ, Wq, 64, tid, 512);
        stage65(fs + OWK, Wk, 64, tid, 512);
    }

    // P0: reduce partials (16 chunks), load old slots
    if (tid < 448) {
        float s = 0.f;
        #pragma unroll
        for (int ch = 0; ch < 16; ch++) s += gP[(b*16 + ch)*448 + tid];
        sxa[tid] = s;          // raw P for now
        sh[tid]  = g_slots[b*448 + tid];
    }
    if (tid < 7) {
        float K = 0.f, D = 0.f;
        #pragma unroll
        for (int ch = 0; ch < 16; ch++) {
            float k0, d0; unpack2(g_KD2[(b*16 + ch)*7 + tid], k0, d0);
            K += k0; D += d0;
        }
        sK[tid] = K; sD[tid] = D;
    }
    __syncthreads();
    // P1: xa = (P-K)/D * g_in + be_in  (in place)
    if (tid < 448) {
        int e = tid & 63, i = tid >> 6;
        sxa[tid] = fmaf((sxa[tid] - sK[i]) / sD[i], gin[e], bein[e]);
    }
    __syncthreads();
    // P2: upd = xa @ Wv^T + bv
    if (tid < 448) {
        int c = tid & 63, i = tid >> 6;
        float a0 = 0.f, a1 = 0.f;
        #pragma unroll 8
        for (int e = 0; e < 64; e += 2) {
            a0 = fmaf(sxa[i*64 + e],   fs[OWV + c*65 + e],   a0);
            a1 = fmaf(sxa[i*64 + e+1], fs[OWV + c*65 + e+1], a1);
        }
        supd[tid] = bv[c] + a0 + a1;
    }
    __syncthreads();
    // P3: fused GRU: 6 dots + gates per (i,c)
    if (tid < 448) {
        int c = tid & 63, i = tid >> 6;
        const float* wir = fs + OWIH + c*65;
        const float* wiz = fs + OWIH + (64 + c)*65;
        const float* win = fs + OWIH + (128 + c)*65;
        const float* whr = fs + OWHH + c*65;
        const float* whz = fs + OWHH + (64 + c)*65;
        const float* whn = fs + OWHH + (128 + c)*65;
        const float* xu = supd + i*64;
        const float* hh = sh + i*64;
        float gir = 0.f, giz = 0.f, gin_ = 0.f, ghr = 0.f, ghz = 0.f, ghn = 0.f;
        #pragma unroll 8
        for (int d = 0; d < 64; d++) {
            float xv = xu[d], hv = hh[d];
            gir = fmaf(xv, wir[d], gir);
            giz = fmaf(xv, wiz[d], giz);
            gin_ = fmaf(xv, win[d], gin_);
            ghr = fmaf(hv, whr[d], ghr);
            ghz = fmaf(hv, whz[d], ghz);
            ghn = fmaf(hv, whn[d], ghn);
        }
        gir += b_ih[c];        ghr += b_hh[c];
        giz += b_ih[64 + c];   ghz += b_hh[64 + c];
        gin_ += b_ih[128 + c]; ghn += b_hh[128 + c];
        float rg = 1.0f / (1.0f + __expf(-(gir + ghr)));
        float zg = 1.0f / (1.0f + __expf(-(giz + ghz)));
        float ng = tanhf(fmaf(rg, ghn, gin_));
        snew[tid] = fmaf(zg, sh[tid] - ng, ng);
    }
    __syncthreads();
    // P4: LN(snew) -> sff (overlays sxa)
    if (w < 7) warp_ln(snew, sff, gff, beff, w, lane);
    __syncthreads();
    // P5: y1 = relu(ff @ W1^T + b1)
    for (int idx = tid; idx < 896; idx += 512) {
        int i = idx >> 7, r = idx & 127;
        float a0 = 0.f, a1 = 0.f;
        #pragma unroll 8
        for (int c = 0; c < 64; c += 2) {
            a0 = fmaf(sff[i*64 + c],   fs[OW1 + r*65 + c],   a0);
            a1 = fmaf(sff[i*64 + c+1], fs[OW1 + r*65 + c+1], a1);
        }
        sy1[idx] = fmaxf(b1[r] + a0 + a1, 0.0f);
    }
    __syncthreads();
    // P6: slots = snew + y1 @ W2^T + b2 -> sh (input to prep)
    if (tid < 448) {
        int c = tid & 63, i = tid >> 6;
        float a0 = 0.f, a1 = 0.f;
        #pragma unroll 8
        for (int r = 0; r < 128; r += 2) {
            a0 = fmaf(sy1[i*128 + r],   fs[OW2 + c*129 + r],   a0);
            a1 = fmaf(sy1[i*128 + r+1], fs[OW2 + c*129 + r+1], a1);
        }
        float v = snew[tid] + b2[c] + a0 + a1;
        g_slots[b*448 + tid] = v;
        sh[tid] = v;
        if (outp) outp[b*448 + tid] = v;
    }
    if (doprep) {
        __syncthreads();
        do_prep(b, tid, fs, bq, bk, gsl, besl, gin, bein);
    }
}

// ---------------------------------------------------------------------------
extern "C" void kernel_launch(void* const* d_in, const int* in_sizes, int n_in,
                              void* d_out, int out_size)
{
    const float* inputs = (const float*)d_in[0];
    const float* noise  = (const float*)d_in[2];
    const float* mu     = (const float*)d_in[3];
    const float* sigma  = (const float*)d_in[4];
    const float* Wq     = (const float*)d_in[5];
    const float* bq     = (const float*)d_in[6];
    const float* Wk     = (const float*)d_in[7];
    const float* bk     = (const float*)d_in[8];
    const float* Wv     = (const float*)d_in[9];
    const float* bv     = (const float*)d_in[10];
    const float* W_ih   = (const float*)d_in[11];
    const float* W_hh   = (const float*)d_in[12];
    const float* b_ih   = (const float*)d_in[13];
    const float* b_hh   = (const float*)d_in[14];
    const float* W1     = (const float*)d_in[15];
    const float* b1     = (const float*)d_in[16];
    const float* W2     = (const float*)d_in[17];
    const float* b2     = (const float*)d_in[18];
    const float* gin    = (const float*)d_in[19];
    const float* bein   = (const float*)d_in[20];
    const float* gsl    = (const float*)d_in[21];
    const float* besl   = (const float*)d_in[22];
    const float* gff    = (const float*)d_in[23];
    const float* beff   = (const float*)d_in[24];

    const int ATTN_SMEM = 5864 * 8;
    static int configured = 0;
    if (!configured) {
        cudaFuncSetAttribute(attn_pass, cudaFuncAttributeMaxDynamicSharedMemorySize, ATTN_SMEM);
        cudaFuncSetAttribute(slot_begin, cudaFuncAttributeMaxDynamicSharedMemorySize, SLOT_SMEM);
        cudaFuncSetAttribute(slot_step, cudaFuncAttributeMaxDynamicSharedMemorySize, SLOT_SMEM);
        configured = 1;
    }

    slot_begin<<<64, 512, SLOT_SMEM>>>(noise, mu, sigma, Wq, bq, Wk, bk,
                                       gsl, besl, gin, bein);
    for (int it = 0; it < 3; it++) {
        attn_pass<<<1024, 128, ATTN_SMEM>>>(inputs);
        slot_step<<<64, 512, SLOT_SMEM>>>(Wv, bv, W_ih, W_hh, b_ih, b_hh,
                                          W1, b1, W2, b2, gin, bein, gff, beff,
                                          Wq, bq, Wk, bk, gsl, besl,
                                          it == 2 ? (float*)d_out : nullptr,
                                          it == 2 ? 0 : 1);
    }
}